// round 8
// baseline (speedup 1.0000x reference)
#include <cuda_runtime.h>
#include <cuda_bf16.h>
#include <cstdint>

#define B 128
#define L 1024
#define E 1280
#define E4 (E/4)     // 320
#define H 128
#define NCH 16
#define CHROWS (L/NCH) // 64

#define NBLK 296
#define NTHR 256
#define GSTRIDE (NBLK*NTHR)

// ---------------- scratch ------------------------------------------------------
__device__ float g_pool_part[B * NCH * E];
__device__ float g_xpool[B * E];
__device__ float g_h[B * 2560];
__device__ float g_P1[4 * B * 2560];
__device__ float g_P2[8 * B * 1280];
__device__ float g_P4[16 * B * 128];
__device__ float g_cross[B * 1280];
__device__ float g_Pf[8 * B * 1024];
__device__ float g_Pf2[8 * B * 128];

__device__ unsigned g_bar_count = 0;
__device__ volatile unsigned g_bar_gen = 0;

// ---------------- grid barrier (sole kernel on GPU; 296 CTAs resident) --------
__device__ __forceinline__ void grid_barrier() {
    __syncthreads();
    if (threadIdx.x == 0) {
        __threadfence();
        unsigned gen = g_bar_gen;
        unsigned a = atomicAdd(&g_bar_count, 1u);
        if (a == NBLK - 1) {
            g_bar_count = 0;
            __threadfence();
            g_bar_gen = gen + 1;
        } else {
            while (g_bar_gen == gen) { }
        }
    }
    __syncthreads();
}

// ---------------- tf32 helpers -------------------------------------------------
__device__ __forceinline__ unsigned f2tf(float x) {
    unsigned r; asm("cvt.rna.tf32.f32 %0, %1;" : "=r"(r) : "f"(x)); return r;
}
__device__ __forceinline__ float4 ldcg4(const float* p) {
    return __ldcg((const float4*)p);
}
__device__ __forceinline__ float4 ldcs4(const float4* p) {
    return __ldcs(p);
}

// A loads bypass L1 (A is an in-kernel-produced intermediate).
template<int KSIN>
__device__ __forceinline__ float4 compose_cg(const float* __restrict__ A,
                                             int row, int K, int kk,
                                             const float* __restrict__ a_bias,
                                             int a_relu)
{
    size_t base = (size_t)row * K + kk;
    float4 s = ldcg4(A + base);
    if (KSIN > 1) {
        size_t slab = (size_t)128 * K;
        #pragma unroll
        for (int ss = 1; ss < KSIN; ++ss) {
            float4 v = ldcg4(A + (size_t)ss * slab + base);
            s.x += v.x; s.y += v.y; s.z += v.z; s.w += v.w;
        }
        if (a_bias) {
            float4 bv = *(const float4*)(a_bias + kk);
            s.x += bv.x; s.y += bv.y; s.z += bv.z; s.w += bv.w;
        }
        if (a_relu) {
            s.x = fmaxf(s.x, 0.f); s.y = fmaxf(s.y, 0.f);
            s.z = fmaxf(s.z, 0.f); s.w = fmaxf(s.w, 0.f);
        }
    }
    return s;
}

// ---------------- one GEMM tile (device function) ------------------------------
// P[kidx][128][N] = A[128, kidx*Kc : +Kc] @ W[..., N] for the 32-wide n_blk.
template<int KSIN>
__device__ __forceinline__ void gemm_tile(
    const float* __restrict__ A, const float* __restrict__ W,
    float* __restrict__ P, const float* __restrict__ a_bias,
    int N, int K, int Kc, int a_relu, int n_blk, int kidx,
    unsigned (&As)[2][128*36], unsigned (&Bs)[2][1024])
{
    int tid = threadIdx.x;
    int warp = tid >> 5;
    int lane = tid & 31;
    int wm = warp >> 1;
    int wn = warp & 1;
    int g  = lane >> 2;
    int tg = lane & 3;

    int k0 = kidx * Kc;
    int arow0 = tid >> 3;
    int akq   = (tid & 7) * 4;
    int wk    = tid >> 3;
    int wn4   = (tid & 7) * 4;
    int wchunk = wn4 >> 3;
    int woff   = wn4 & 7;

    float acc[2][2][4];
    #pragma unroll
    for (int mt = 0; mt < 2; ++mt)
        #pragma unroll
        for (int nt = 0; nt < 2; ++nt)
            #pragma unroll
            for (int i = 0; i < 4; ++i) acc[mt][nt][i] = 0.f;

    float4 av[4]; float4 wv;

    #pragma unroll
    for (int j = 0; j < 4; ++j)
        av[j] = compose_cg<KSIN>(A, arow0 + 32 * j, K, k0 + akq, a_bias, a_relu);
    wv = *(const float4*)(W + (size_t)(k0 + wk) * N + n_blk + wn4);
    #pragma unroll
    for (int j = 0; j < 4; ++j) {
        unsigned* ap = &As[0][(arow0 + 32 * j) * 36 + akq];
        ap[0] = f2tf(av[j].x); ap[1] = f2tf(av[j].y);
        ap[2] = f2tf(av[j].z); ap[3] = f2tf(av[j].w);
    }
    {
        unsigned* bp = &Bs[0][wchunk * 256 + wk * 8 + woff];
        bp[0] = f2tf(wv.x); bp[1] = f2tf(wv.y);
        bp[2] = f2tf(wv.z); bp[3] = f2tf(wv.w);
    }

    int niter = Kc >> 5;
    int buf = 0;
    for (int it = 0; it < niter; ++it) {
        __syncthreads();
        bool has_next = (it + 1 < niter);
        if (has_next) {
            int kt = k0 + (it + 1) * 32;
            #pragma unroll
            for (int j = 0; j < 4; ++j)
                av[j] = compose_cg<KSIN>(A, arow0 + 32 * j, K, kt + akq, a_bias, a_relu);
            wv = *(const float4*)(W + (size_t)(kt + wk) * N + n_blk + wn4);
        }

        const unsigned* Ab = As[buf];
        const unsigned* Bb = Bs[buf];
        #pragma unroll
        for (int ks = 0; ks < 4; ++ks) {
            int k = ks * 8;
            unsigned a[2][4], bf[2][2];
            #pragma unroll
            for (int mt = 0; mt < 2; ++mt) {
                int r = wm * 32 + mt * 16 + g;
                a[mt][0] = Ab[r * 36 + k + tg];
                a[mt][1] = Ab[(r + 8) * 36 + k + tg];
                a[mt][2] = Ab[r * 36 + k + tg + 4];
                a[mt][3] = Ab[(r + 8) * 36 + k + tg + 4];
            }
            #pragma unroll
            for (int nt = 0; nt < 2; ++nt) {
                int c = wn * 2 + nt;
                bf[nt][0] = Bb[c * 256 + (k + tg) * 8 + g];
                bf[nt][1] = Bb[c * 256 + (k + tg + 4) * 8 + g];
            }
            #pragma unroll
            for (int mt = 0; mt < 2; ++mt)
                #pragma unroll
                for (int nt = 0; nt < 2; ++nt) {
                    asm volatile(
                        "mma.sync.aligned.m16n8k8.row.col.f32.tf32.tf32.f32 "
                        "{%0,%1,%2,%3}, {%4,%5,%6,%7}, {%8,%9}, {%0,%1,%2,%3};\n"
                        : "+f"(acc[mt][nt][0]), "+f"(acc[mt][nt][1]),
                          "+f"(acc[mt][nt][2]), "+f"(acc[mt][nt][3])
                        : "r"(a[mt][0]), "r"(a[mt][1]), "r"(a[mt][2]), "r"(a[mt][3]),
                          "r"(bf[nt][0]), "r"(bf[nt][1]));
                }
        }

        if (has_next) {
            unsigned* Aw = As[buf ^ 1];
            unsigned* Bw = Bs[buf ^ 1];
            #pragma unroll
            for (int j = 0; j < 4; ++j) {
                unsigned* ap = &Aw[(arow0 + 32 * j) * 36 + akq];
                ap[0] = f2tf(av[j].x); ap[1] = f2tf(av[j].y);
                ap[2] = f2tf(av[j].z); ap[3] = f2tf(av[j].w);
            }
            unsigned* bp = &Bw[wchunk * 256 + wk * 8 + woff];
            bp[0] = f2tf(wv.x); bp[1] = f2tf(wv.y);
            bp[2] = f2tf(wv.z); bp[3] = f2tf(wv.w);
        }
        buf ^= 1;
    }

    float* dst = P + (size_t)kidx * 128 * N + n_blk;
    #pragma unroll
    for (int mt = 0; mt < 2; ++mt) {
        int row = wm * 32 + mt * 16 + g;
        #pragma unroll
        for (int nt = 0; nt < 2; ++nt) {
            int nloc = wn * 16 + nt * 8 + tg * 2;
            *(float2*)(dst + (size_t)row * N + nloc) =
                make_float2(acc[mt][nt][0], acc[mt][nt][1]);
            *(float2*)(dst + (size_t)(row + 8) * N + nloc) =
                make_float2(acc[mt][nt][2], acc[mt][nt][3]);
        }
    }
}

// ---------------- split-K reduce stage ----------------------------------------
template<int KS>
__device__ __forceinline__ void reduce_stage(const float* __restrict__ P,
                                             const float* __restrict__ bias,
                                             float* __restrict__ out,
                                             int MN4, int N4, int relu, int gtid)
{
    for (int i = gtid; i < MN4; i += GSTRIDE) {
        float4 v[KS];
        #pragma unroll
        for (int s = 0; s < KS; ++s)
            v[s] = __ldcg(((const float4*)P) + (size_t)s * MN4 + i);
        float4 a = v[0];
        #pragma unroll
        for (int s = 1; s < KS; ++s) {
            a.x += v[s].x; a.y += v[s].y; a.z += v[s].z; a.w += v[s].w;
        }
        if (bias) {
            float4 bv = ((const float4*)bias)[i % N4];
            a.x += bv.x; a.y += bv.y; a.z += bv.z; a.w += bv.w;
        }
        if (relu) {
            a.x = fmaxf(a.x, 0.f); a.y = fmaxf(a.y, 0.f);
            a.z = fmaxf(a.z, 0.f); a.w = fmaxf(a.w, 0.f);
        }
        ((float4*)out)[i] = a;
    }
}

// ---------------- THE kernel ---------------------------------------------------
__global__ __launch_bounds__(NTHR, 2) void fused_all_kernel(
    const float* __restrict__ esm, const int* __restrict__ vlens,
    const float* __restrict__ modal_a, const float* __restrict__ modal_b,
    const float* __restrict__ layer_w1, const float* __restrict__ layer_b1,
    const float* __restrict__ layer_w2, const float* __restrict__ layer_b2,
    const float* __restrict__ mlp_w1,   const float* __restrict__ mlp_b1,
    const float* __restrict__ mlp_w2,   const float* __restrict__ mlp_b2,
    const float* __restrict__ fe_w1,    const float* __restrict__ fe_w2,
    const float* __restrict__ fe_b2,
    const float* __restrict__ lnf_g,    const float* __restrict__ lnf_b,
    float* __restrict__ out_x, float* __restrict__ out_px,
    float* __restrict__ out_pf)
{
    __shared__ unsigned As[2][128 * 36];
    __shared__ unsigned Bs[2][1024];
    int bid  = blockIdx.x;
    int gtid = bid * NTHR + threadIdx.x;
    int lane = threadIdx.x & 31;

    // ---- stage 0: standardize(modal_a|modal_b) -> g_cross   AND pool partials
    for (int col = gtid; col < 1280; col += GSTRIDE) {
        const float* src; int nc, c;
        if (col < 512) { src = modal_a; nc = 512; c = col; }
        else           { src = modal_b; nc = 768; c = col - 512; }
        float sum = 0.f, sumsq = 0.f;
        for (int r = 0; r < B; ++r) {
            float v = src[(size_t)r * nc + c];
            sum += v; sumsq += v * v;
        }
        float mean = sum * (1.0f / 128.0f);
        float var  = (sumsq - sum * mean) * (1.0f / 127.0f);   // ddof=1
        float inv  = rsqrtf(var);
        for (int r = 0; r < B; ++r) {
            float v = src[(size_t)r * nc + c];
            g_cross[(size_t)r * 1280 + col] = (v - mean) * inv;
        }
    }
    for (int task = bid; task < B * NCH; task += NBLK) {
        int c = task >> 7;
        int b = task & 127;
        int len = vlens[b] + 2;
        int r0 = c * CHROWS;
        int r1 = min(r0 + CHROWS, len);
        const float4* base = (const float4*)(esm + (size_t)b * L * E);
        for (int ln = threadIdx.x; ln < E4; ln += NTHR) {
            float4 s0 = make_float4(0.f,0.f,0.f,0.f), s1 = s0, s2 = s0, s3 = s0;
            int r = r0;
            for (; r + 4 <= r1; r += 4) {
                float4 v0 = ldcs4(base + (size_t)(r+0) * E4 + ln);
                float4 v1 = ldcs4(base + (size_t)(r+1) * E4 + ln);
                float4 v2 = ldcs4(base + (size_t)(r+2) * E4 + ln);
                float4 v3 = ldcs4(base + (size_t)(r+3) * E4 + ln);
                s0.x+=v0.x; s0.y+=v0.y; s0.z+=v0.z; s0.w+=v0.w;
                s1.x+=v1.x; s1.y+=v1.y; s1.z+=v1.z; s1.w+=v1.w;
                s2.x+=v2.x; s2.y+=v2.y; s2.z+=v2.z; s2.w+=v2.w;
                s3.x+=v3.x; s3.y+=v3.y; s3.z+=v3.z; s3.w+=v3.w;
            }
            for (; r < r1; ++r) {
                float4 v = ldcs4(base + (size_t)r * E4 + ln);
                s0.x+=v.x; s0.y+=v.y; s0.z+=v.z; s0.w+=v.w;
            }
            s0.x += s1.x + s2.x + s3.x;
            s0.y += s1.y + s2.y + s3.y;
            s0.z += s1.z + s2.z + s3.z;
            s0.w += s1.w + s2.w + s3.w;
            ((float4*)g_pool_part)[((size_t)b * NCH + c) * E4 + ln] = s0;
        }
    }
    grid_barrier();

    // ---- stage 1: pool reduce -> g_xpool   AND fe_gemm1 (cross @ fe_w1 -> Pf)
    for (int i = gtid; i < B * E4; i += GSTRIDE) {
        int b = i / E4, t = i - b * E4;
        float inv = 1.0f / (float)(vlens[b] + 2);
        float4 s = make_float4(0.f, 0.f, 0.f, 0.f);
        #pragma unroll
        for (int c = 0; c < NCH; ++c) {
            float4 v = ldcg4(g_pool_part + (((size_t)b * NCH + c) * E4 + t) * 4);
            s.x += v.x; s.y += v.y; s.z += v.z; s.w += v.w;
        }
        s.x *= inv; s.y *= inv; s.z *= inv; s.w *= inv;
        ((float4*)g_xpool)[i] = s;
    }
    for (int tile = bid; tile < 256; tile += NBLK) {
        __syncthreads();
        gemm_tile<1>(g_cross, fe_w1, g_Pf, nullptr,
                     1024, 1280, 160, 0, (tile & 31) * 32, tile >> 5, As, Bs);
    }
    grid_barrier();

    // ---- stage 2: gemm1 (xpool @ layer_w1 -> P1)  AND fe_gemm2 (relu(sum Pf) @ fe_w2 -> Pf2)
    for (int tile = bid; tile < 352; tile += NBLK) {
        __syncthreads();
        if (tile < 320) {
            gemm_tile<1>(g_xpool, layer_w1, g_P1, nullptr,
                         2560, 1280, 320, 0, (tile % 80) * 32, tile / 80, As, Bs);
        } else {
            int t2 = tile - 320;
            gemm_tile<8>(g_Pf, fe_w2, g_Pf2, nullptr,
                         128, 1024, 128, 1, (t2 & 3) * 32, t2 >> 2, As, Bs);
        }
    }
    grid_barrier();

    // ---- stage 3: reduce4+bias+relu -> g_h   AND reduce8+bias+LN -> out_pf
    reduce_stage<4>(g_P1, layer_b1, g_h, B * 2560 / 4, 640, 1, gtid);
    {
        int wg = gtid >> 5;
        if (wg < B) {
            int row = wg;
            float s[4];
            #pragma unroll
            for (int j = 0; j < 4; ++j) {
                int col = j * 32 + lane;
                float acc = fe_b2[col];
                #pragma unroll
                for (int ks = 0; ks < 8; ++ks)
                    acc += __ldcg(&g_Pf2[(size_t)ks * (B * H) + (size_t)row * H + col]);
                s[j] = acc;
            }
            float tot = s[0] + s[1] + s[2] + s[3];
            #pragma unroll
            for (int o = 16; o > 0; o >>= 1) tot += __shfl_xor_sync(0xffffffffu, tot, o);
            float mean = tot * (1.0f / 128.0f);
            float sq = 0.f;
            #pragma unroll
            for (int j = 0; j < 4; ++j) { float d = s[j] - mean; sq += d * d; }
            #pragma unroll
            for (int o = 16; o > 0; o >>= 1) sq += __shfl_xor_sync(0xffffffffu, sq, o);
            float inv = rsqrtf(sq * (1.0f / 128.0f) + 1e-5f);
            #pragma unroll
            for (int j = 0; j < 4; ++j) {
                int col = j * 32 + lane;
                out_pf[(size_t)row * H + col] =
                    (s[j] - mean) * inv * lnf_g[col] + lnf_b[col];
            }
        }
    }
    grid_barrier();

    // ---- stage 4: gemm2 (h @ layer_w2 -> P2)
    for (int tile = bid; tile < 320; tile += NBLK) {
        __syncthreads();
        gemm_tile<1>(g_h, layer_w2, g_P2, nullptr,
                     1280, 2560, 320, 0, (tile % 40) * 32, tile / 40, As, Bs);
    }
    grid_barrier();

    // ---- stage 5: reduce8 + bias -> out_x
    reduce_stage<8>(g_P2, layer_b2, out_x, B * 1280 / 4, 320, 0, gtid);
    grid_barrier();

    // ---- stage 6: gemm3 (out_x @ mlp_w1 -> P1)
    for (int tile = bid; tile < 320; tile += NBLK) {
        __syncthreads();
        gemm_tile<1>(out_x, mlp_w1, g_P1, nullptr,
                     2560, 1280, 320, 0, (tile % 80) * 32, tile / 80, As, Bs);
    }
    grid_barrier();

    // ---- stage 7: gemm4  relu(b1 + sum P1) @ mlp_w2 -> P4
    for (int tile = bid; tile < 64; tile += NBLK) {
        __syncthreads();
        gemm_tile<4>(g_P1, mlp_w2, g_P4, mlp_b1,
                     128, 2560, 160, 1, (tile & 3) * 32, tile >> 2, As, Bs);
    }
    grid_barrier();

    // ---- stage 8: reduce16 + bias -> out_px
    reduce_stage<16>(g_P4, mlp_b2, out_px, B * 128 / 4, 32, 0, gtid);
}

// ---------------- launch ------------------------------------------------------
extern "C" void kernel_launch(void* const* d_in, const int* in_sizes, int n_in,
                              void* d_out, int out_size)
{
    const float* esm      = (const float*)d_in[0];
    const int*   vlens    = (const int*)  d_in[1];
    const float* modal_a  = (const float*)d_in[2];
    const float* modal_b  = (const float*)d_in[3];
    const float* layer_w1 = (const float*)d_in[4];
    const float* layer_b1 = (const float*)d_in[5];
    const float* layer_w2 = (const float*)d_in[6];
    const float* layer_b2 = (const float*)d_in[7];
    const float* mlp_w1   = (const float*)d_in[8];
    const float* mlp_b1   = (const float*)d_in[9];
    const float* mlp_w2   = (const float*)d_in[10];
    const float* mlp_b2   = (const float*)d_in[11];
    const float* fe_w1    = (const float*)d_in[12];
    const float* fe_w2    = (const float*)d_in[13];
    const float* fe_b2    = (const float*)d_in[14];
    const float* lnf_g    = (const float*)d_in[15];
    const float* lnf_b    = (const float*)d_in[16];

    float* out_x  = (float*)d_out;
    float* out_px = out_x + B * E;
    float* out_pf = out_px + B * H;

    fused_all_kernel<<<NBLK, NTHR>>>(esm, vlens, modal_a, modal_b,
                                     layer_w1, layer_b1, layer_w2, layer_b2,
                                     mlp_w1, mlp_b1, mlp_w2, mlp_b2,
                                     fe_w1, fe_w2, fe_b2, lnf_g, lnf_b,
                                     out_x, out_px, out_pf);
}

// round 13
// speedup vs baseline: 1.1061x; 1.1061x over previous
#include <cuda_runtime.h>
#include <cuda_bf16.h>
#include <cstdint>

#define B 128
#define L 1024
#define E 1280
#define E4 (E/4)     // 320
#define H 128
#define NCH 16
#define CHROWS (L/NCH) // 64

// ---------------- scratch ------------------------------------------------------
__device__ float g_pool_part[B * NCH * E];
__device__ float g_xpool[B * E];
__device__ float g_h[B * 2560];
__device__ float g_P1[4 * B * 2560];
__device__ float g_P2[8 * B * 1280];
__device__ float g_P4[16 * B * 128];
__device__ float g_cross[B * 1280];
__device__ float g_Pf[8 * B * 1024];
__device__ float g_Pf2[8 * B * 128];

// ---------------- helpers ------------------------------------------------------
__device__ __forceinline__ unsigned f2tf(float x) {
    unsigned r; asm("cvt.rna.tf32.f32 %0, %1;" : "=r"(r) : "f"(x)); return r;
}
__device__ __forceinline__ float4 ldcs4(const float4* p) { return __ldcs(p); }
__device__ __forceinline__ void add4(float4& a, const float4 b) {
    a.x += b.x; a.y += b.y; a.z += b.z; a.w += b.w;
}

// ---------------- pool partials: DRAM-streaming, MLP 8 -------------------------
__global__ __launch_bounds__(320) void pool_partial_kernel(
    const float* __restrict__ esm, const int* __restrict__ vlens)
{
    int c = blockIdx.x >> 7;        // chunk
    int b = blockIdx.x & 127;       // batch row
    int t = threadIdx.x;            // 320 lanes, one float4 each
    int len = vlens[b] + 2;
    int r0 = c * CHROWS;
    int r1 = min(r0 + CHROWS, len);
    const float4* base = (const float4*)(esm + (size_t)b * L * E);
    float4 s0 = make_float4(0.f,0.f,0.f,0.f), s1 = s0, s2 = s0, s3 = s0;
    float4 s4 = s0, s5 = s0, s6 = s0, s7 = s0;
    int r = r0;
    for (; r + 8 <= r1; r += 8) {
        float4 v0 = ldcs4(base + (size_t)(r+0) * E4 + t);
        float4 v1 = ldcs4(base + (size_t)(r+1) * E4 + t);
        float4 v2 = ldcs4(base + (size_t)(r+2) * E4 + t);
        float4 v3 = ldcs4(base + (size_t)(r+3) * E4 + t);
        float4 v4 = ldcs4(base + (size_t)(r+4) * E4 + t);
        float4 v5 = ldcs4(base + (size_t)(r+5) * E4 + t);
        float4 v6 = ldcs4(base + (size_t)(r+6) * E4 + t);
        float4 v7 = ldcs4(base + (size_t)(r+7) * E4 + t);
        add4(s0, v0); add4(s1, v1); add4(s2, v2); add4(s3, v3);
        add4(s4, v4); add4(s5, v5); add4(s6, v6); add4(s7, v7);
    }
    for (; r < r1; ++r) add4(s0, ldcs4(base + (size_t)r * E4 + t));
    add4(s0, s1); add4(s2, s3); add4(s4, s5); add4(s6, s7);
    add4(s0, s2); add4(s4, s6); add4(s0, s4);
    ((float4*)g_pool_part)[((size_t)b * NCH + c) * E4 + t] = s0;
}

__global__ void pool_reduce_kernel(const int* __restrict__ vlens) {
    int b = blockIdx.x;
    int t = threadIdx.x;            // 320 threads
    float inv = 1.0f / (float)(vlens[b] + 2);
    float4 s = make_float4(0.f, 0.f, 0.f, 0.f);
    #pragma unroll
    for (int c = 0; c < NCH; ++c) {
        float4 v = ((const float4*)g_pool_part)[((size_t)b * NCH + c) * E4 + t];
        add4(s, v);
    }
    s.x *= inv; s.y *= inv; s.z *= inv; s.w *= inv;
    ((float4*)g_xpool)[(size_t)b * E4 + t] = s;
}

// ---------------- tf32 tensor-core GEMM, double-buffered ----------------------
// P[ks][128][N] partial = A[128, k0:k0+Kc] @ W[k0:k0+Kc, N].
// A may be a composed split-K stack: A = act(bias + sum_KSIN slabs).
template<int KSIN>
__device__ __forceinline__ float4 load_composeA(const float* __restrict__ A,
                                                int row, int K, int kk,
                                                const float* __restrict__ a_bias,
                                                int a_relu)
{
    size_t base = (size_t)row * K + kk;
    float4 s = *(const float4*)(A + base);
    if (KSIN > 1) {
        size_t slab = (size_t)128 * K;
        #pragma unroll
        for (int ss = 1; ss < KSIN; ++ss) {
            float4 v = *(const float4*)(A + (size_t)ss * slab + base);
            add4(s, v);
        }
        if (a_bias) {
            float4 bv = *(const float4*)(a_bias + kk);
            add4(s, bv);
        }
        if (a_relu) {
            s.x = fmaxf(s.x, 0.f); s.y = fmaxf(s.y, 0.f);
            s.z = fmaxf(s.z, 0.f); s.w = fmaxf(s.w, 0.f);
        }
    }
    return s;
}

template<int KSIN>
__global__ __launch_bounds__(256, 2) void gemm_tc_kernel(
    const float* __restrict__ A, const float* __restrict__ W,
    float* __restrict__ P, const float* __restrict__ a_bias,
    int N, int K, int Kc, int a_relu)
{
    __shared__ unsigned As[2][128 * 36];
    __shared__ unsigned Bs[2][1024];

    int tid = threadIdx.x;
    int warp = tid >> 5;
    int lane = tid & 31;
    int wm = warp >> 1;
    int wn = warp & 1;
    int g  = lane >> 2;
    int tg = lane & 3;

    int n_blk = blockIdx.x * 32;
    int k0 = blockIdx.y * Kc;

    int arow0 = tid >> 3;
    int akq   = (tid & 7) * 4;
    int wk    = tid >> 3;
    int wn4   = (tid & 7) * 4;
    int wchunk = wn4 >> 3;
    int woff   = wn4 & 7;

    float acc[2][2][4];
    #pragma unroll
    for (int mt = 0; mt < 2; ++mt)
        #pragma unroll
        for (int nt = 0; nt < 2; ++nt)
            #pragma unroll
            for (int i = 0; i < 4; ++i) acc[mt][nt][i] = 0.f;

    float4 av[4]; float4 wv;

    #pragma unroll
    for (int j = 0; j < 4; ++j)
        av[j] = load_composeA<KSIN>(A, arow0 + 32 * j, K, k0 + akq, a_bias, a_relu);
    wv = *(const float4*)(W + (size_t)(k0 + wk) * N + n_blk + wn4);
    #pragma unroll
    for (int j = 0; j < 4; ++j) {
        unsigned* ap = &As[0][(arow0 + 32 * j) * 36 + akq];
        ap[0] = f2tf(av[j].x); ap[1] = f2tf(av[j].y);
        ap[2] = f2tf(av[j].z); ap[3] = f2tf(av[j].w);
    }
    {
        unsigned* bp = &Bs[0][wchunk * 256 + wk * 8 + woff];
        bp[0] = f2tf(wv.x); bp[1] = f2tf(wv.y);
        bp[2] = f2tf(wv.z); bp[3] = f2tf(wv.w);
    }

    int niter = Kc >> 5;
    int buf = 0;
    for (int it = 0; it < niter; ++it) {
        __syncthreads();
        bool has_next = (it + 1 < niter);
        if (has_next) {
            int kt = k0 + (it + 1) * 32;
            #pragma unroll
            for (int j = 0; j < 4; ++j)
                av[j] = load_composeA<KSIN>(A, arow0 + 32 * j, K, kt + akq, a_bias, a_relu);
            wv = *(const float4*)(W + (size_t)(kt + wk) * N + n_blk + wn4);
        }

        const unsigned* Ab = As[buf];
        const unsigned* Bb = Bs[buf];
        #pragma unroll
        for (int ks = 0; ks < 4; ++ks) {
            int k = ks * 8;
            unsigned a[2][4], bf[2][2];
            #pragma unroll
            for (int mt = 0; mt < 2; ++mt) {
                int r = wm * 32 + mt * 16 + g;
                a[mt][0] = Ab[r * 36 + k + tg];
                a[mt][1] = Ab[(r + 8) * 36 + k + tg];
                a[mt][2] = Ab[r * 36 + k + tg + 4];
                a[mt][3] = Ab[(r + 8) * 36 + k + tg + 4];
            }
            #pragma unroll
            for (int nt = 0; nt < 2; ++nt) {
                int c = wn * 2 + nt;
                bf[nt][0] = Bb[c * 256 + (k + tg) * 8 + g];
                bf[nt][1] = Bb[c * 256 + (k + tg + 4) * 8 + g];
            }
            #pragma unroll
            for (int mt = 0; mt < 2; ++mt)
                #pragma unroll
                for (int nt = 0; nt < 2; ++nt) {
                    asm volatile(
                        "mma.sync.aligned.m16n8k8.row.col.f32.tf32.tf32.f32 "
                        "{%0,%1,%2,%3}, {%4,%5,%6,%7}, {%8,%9}, {%0,%1,%2,%3};\n"
                        : "+f"(acc[mt][nt][0]), "+f"(acc[mt][nt][1]),
                          "+f"(acc[mt][nt][2]), "+f"(acc[mt][nt][3])
                        : "r"(a[mt][0]), "r"(a[mt][1]), "r"(a[mt][2]), "r"(a[mt][3]),
                          "r"(bf[nt][0]), "r"(bf[nt][1]));
                }
        }

        if (has_next) {
            unsigned* Aw = As[buf ^ 1];
            unsigned* Bw = Bs[buf ^ 1];
            #pragma unroll
            for (int j = 0; j < 4; ++j) {
                unsigned* ap = &Aw[(arow0 + 32 * j) * 36 + akq];
                ap[0] = f2tf(av[j].x); ap[1] = f2tf(av[j].y);
                ap[2] = f2tf(av[j].z); ap[3] = f2tf(av[j].w);
            }
            unsigned* bp = &Bw[wchunk * 256 + wk * 8 + woff];
            bp[0] = f2tf(wv.x); bp[1] = f2tf(wv.y);
            bp[2] = f2tf(wv.z); bp[3] = f2tf(wv.w);
        }
        buf ^= 1;
    }

    float* dst = P + (size_t)blockIdx.y * 128 * N + n_blk;
    #pragma unroll
    for (int mt = 0; mt < 2; ++mt) {
        int row = wm * 32 + mt * 16 + g;
        #pragma unroll
        for (int nt = 0; nt < 2; ++nt) {
            int nloc = wn * 16 + nt * 8 + tg * 2;
            *(float2*)(dst + (size_t)row * N + nloc) =
                make_float2(acc[mt][nt][0], acc[mt][nt][1]);
            *(float2*)(dst + (size_t)(row + 8) * N + nloc) =
                make_float2(acc[mt][nt][2], acc[mt][nt][3]);
        }
    }
}

// ---------------- split-K reduce, templated for full ILP ----------------------
template<int KS>
__global__ void reduce_kernel(const float* __restrict__ P,
                              const float* __restrict__ bias,
                              float* __restrict__ out,
                              int MN4, int N4, int relu)
{
    int i = blockIdx.x * 256 + threadIdx.x;
    if (i >= MN4) return;
    float4 v[KS];
    #pragma unroll
    for (int s = 0; s < KS; ++s) v[s] = ((const float4*)P)[(size_t)s * MN4 + i];
    float4 a = v[0];
    #pragma unroll
    for (int s = 1; s < KS; ++s) add4(a, v[s]);
    if (bias) {
        float4 bv = ((const float4*)bias)[i % N4];
        add4(a, bv);
    }
    if (relu) {
        a.x = fmaxf(a.x, 0.f); a.y = fmaxf(a.y, 0.f);
        a.z = fmaxf(a.z, 0.f); a.w = fmaxf(a.w, 0.f);
    }
    ((float4*)out)[i] = a;
}

// ---------------- block reduce helper -----------------------------------------
__device__ __forceinline__ float block_reduce_128(float v, float* sh) {
    int t = threadIdx.x;
    sh[t] = v;
    __syncthreads();
    #pragma unroll
    for (int s = 64; s > 0; s >>= 1) {
        if (t < s) sh[t] += sh[t + s];
        __syncthreads();
    }
    float r = sh[0];
    __syncthreads();
    return r;
}

// ---------------- fused standardize of modal_a | modal_b ----------------------
// warp per column, 8 warps/block, 160 blocks = 1280 cols
__global__ __launch_bounds__(256) void std_ab_kernel(
    const float* __restrict__ a, const float* __restrict__ bsrc,
    float* __restrict__ cross)
{
    int warp = threadIdx.x >> 5;
    int lane = threadIdx.x & 31;
    int col = blockIdx.x * 8 + warp;
    const float* src; int nc, c;
    if (col < 512) { src = a;    nc = 512; c = col; }
    else           { src = bsrc; nc = 768; c = col - 512; }
    float v[4];
    float sum = 0.f, sumsq = 0.f;
    #pragma unroll
    for (int j = 0; j < 4; ++j) {
        int r = j * 32 + lane;
        v[j] = src[(size_t)r * nc + c];
        sum += v[j]; sumsq += v[j] * v[j];
    }
    #pragma unroll
    for (int o = 16; o > 0; o >>= 1) {
        sum   += __shfl_xor_sync(0xffffffffu, sum, o);
        sumsq += __shfl_xor_sync(0xffffffffu, sumsq, o);
    }
    float mean = sum * (1.0f / 128.0f);
    float var  = (sumsq - sum * mean) * (1.0f / 127.0f);   // ddof=1
    float inv  = rsqrtf(var);
    #pragma unroll
    for (int j = 0; j < 4; ++j) {
        int r = j * 32 + lane;
        cross[(size_t)r * 1280 + col] = (v[j] - mean) * inv;
    }
}

// ---------------- fused split-K reduce + bias + layernorm ---------------------
__global__ void reduce_ln_kernel(const float* __restrict__ P,
                                 const float* __restrict__ bias,
                                 const float* __restrict__ g,
                                 const float* __restrict__ bta,
                                 float* __restrict__ out)
{
    __shared__ float sh[128];
    int row = blockIdx.x;
    int t = threadIdx.x;            // H = 128 cols
    float s = bias[t];
    #pragma unroll
    for (int ks = 0; ks < 8; ++ks)
        s += P[(size_t)ks * (B * H) + (size_t)row * H + t];
    float mean = block_reduce_128(s, sh) * (1.0f / 128.0f);
    float d = s - mean;
    float var = block_reduce_128(d * d, sh) * (1.0f / 128.0f);
    out[(size_t)row * H + t] = d * rsqrtf(var + 1e-5f) * g[t] + bta[t];
}

// ---------------- launch ------------------------------------------------------
extern "C" void kernel_launch(void* const* d_in, const int* in_sizes, int n_in,
                              void* d_out, int out_size)
{
    const float* esm      = (const float*)d_in[0];
    const int*   vlens    = (const int*)  d_in[1];
    const float* modal_a  = (const float*)d_in[2];
    const float* modal_b  = (const float*)d_in[3];
    const float* layer_w1 = (const float*)d_in[4];
    const float* layer_b1 = (const float*)d_in[5];
    const float* layer_w2 = (const float*)d_in[6];
    const float* layer_b2 = (const float*)d_in[7];
    const float* mlp_w1   = (const float*)d_in[8];
    const float* mlp_b1   = (const float*)d_in[9];
    const float* mlp_w2   = (const float*)d_in[10];
    const float* mlp_b2   = (const float*)d_in[11];
    const float* fe_w1    = (const float*)d_in[12];
    const float* fe_w2    = (const float*)d_in[13];
    const float* fe_b2    = (const float*)d_in[14];
    const float* lnf_g    = (const float*)d_in[15];
    const float* lnf_b    = (const float*)d_in[16];

    float* out_x  = (float*)d_out;
    float* out_px = out_x + B * E;
    float* out_pf = out_px + B * H;

    float* xpool = nullptr; cudaGetSymbolAddress((void**)&xpool, g_xpool);
    float* hbuf  = nullptr; cudaGetSymbolAddress((void**)&hbuf,  g_h);
    float* P1    = nullptr; cudaGetSymbolAddress((void**)&P1,    g_P1);
    float* P2    = nullptr; cudaGetSymbolAddress((void**)&P2,    g_P2);
    float* P4    = nullptr; cudaGetSymbolAddress((void**)&P4,    g_P4);
    float* cross = nullptr; cudaGetSymbolAddress((void**)&cross, g_cross);
    float* Pf    = nullptr; cudaGetSymbolAddress((void**)&Pf,    g_Pf);
    float* Pf2   = nullptr; cudaGetSymbolAddress((void**)&Pf2,   g_Pf2);

    // ---- fork a side stream for the independent multimodal branch ----
    cudaStream_t s2;
    cudaStreamCreate(&s2);                 // host resource; leaked (few calls only)
    cudaEvent_t ev_fork, ev_join;
    cudaEventCreateWithFlags(&ev_fork, cudaEventDisableTiming);
    cudaEventCreateWithFlags(&ev_join, cudaEventDisableTiming);

    cudaEventRecord(ev_fork, 0);
    cudaStreamWaitEvent(s2, ev_fork, 0);

    // ---- branch B (multimodal) on s2, overlaps pool + main chain ----
    std_ab_kernel<<<160, 256, 0, s2>>>(modal_a, modal_b, cross);
    gemm_tc_kernel<1><<<dim3(32, 8), 256, 0, s2>>>(cross, fe_w1, Pf, nullptr,
                                                   1024, 1280, 160, 0);
    gemm_tc_kernel<8><<<dim3(4, 8), 256, 0, s2>>>(Pf, fe_w2, Pf2, nullptr,
                                                  128, 1024, 128, 1);
    reduce_ln_kernel<<<B, 128, 0, s2>>>(Pf2, fe_b2, lnf_g, lnf_b, out_pf);
    cudaEventRecord(ev_join, s2);

    // ---- main chain on default stream ----
    pool_partial_kernel<<<2048, 320>>>(esm, vlens);
    pool_reduce_kernel<<<B, 320>>>(vlens);

    // layers: relu(x@W1+b1)@W2+b2 -> out_x
    gemm_tc_kernel<1><<<dim3(80, 4), 256>>>(xpool, layer_w1, P1, nullptr,
                                            2560, 1280, 320, 0);
    reduce_kernel<4><<<320, 256>>>(P1, layer_b1, hbuf, B*2560/4, 2560/4, 1);
    gemm_tc_kernel<1><<<dim3(40, 8), 256>>>(hbuf, layer_w2, P2, nullptr,
                                            1280, 2560, 320, 0);
    reduce_kernel<8><<<160, 256>>>(P2, layer_b2, out_x, B*1280/4, 1280/4, 0);

    // mlp: relu(out_x@W1+b1)@W2+b2 -> out_px  (final reduce fused into gemm A-path)
    gemm_tc_kernel<1><<<dim3(80, 4), 256>>>(out_x, mlp_w1, P1, nullptr,
                                            2560, 1280, 320, 0);
    gemm_tc_kernel<4><<<dim3(4, 16), 256>>>(P1, mlp_w2, P4, mlp_b1,
                                            128, 2560, 160, 1);
    reduce_kernel<16><<<16, 256>>>(P4, mlp_b2, out_px, B*128/4, 128/4, 0);

    // ---- join ----
    cudaStreamWaitEvent(0, ev_join, 0);
}